// round 7
// baseline (speedup 1.0000x reference)
#include <cuda_runtime.h>

#define Bsz     32
#define Anch    3
#define Hd      160
#define Wd      160
#define NT      512
#define NCLS    3
#define PLANE   (Hd*Wd)                 // 25600
#define CONF_ELEMS (Bsz*Anch*PLANE)     // 2,457,600
#define CONF_V4 (CONF_ELEMS/4)          // 614,400
#define PLANE_V4 (PLANE/4)              // 6400

#define NBLOCK  296
#define NTHREAD 512
#define NTH     (NBLOCK*NTHREAD)        // 151,552
#define NWARPS  (NTHREAD/32)            // 16
#define REM     (CONF_V4 - 4*NTH)       // 8,192

// per-block partial sums: [block][0..4] = conf_ss, conf_corr, box, cls, n
__device__ double g_partial[NBLOCK * 5];
__device__ unsigned int g_done;

__device__ __forceinline__ float sigm(float x) {
    return __fdividef(1.0f, 1.0f + __expf(-x));
}

__device__ __forceinline__ int conf_addr(int idx) {
    // conf plane p=b*3+a lives at channel 8*p+4; float4 index mapping:
    return idx + (idx / PLANE_V4) * 44800 + 25600;
}

__device__ __forceinline__ float ssq4(float4 v) {
    float s0 = sigm(v.x), s1 = sigm(v.y), s2 = sigm(v.z), s3 = sigm(v.w);
    return s0*s0 + s1*s1 + s2*s2 + s3*s3;
}

__global__ void __launch_bounds__(NTHREAD)
detection_loss_kernel(const float* __restrict__ pred,
                      const float* __restrict__ targets,
                      float* __restrict__ out)
{
    const int tid = blockIdx.x * NTHREAD + threadIdx.x;

    double acc[5] = {0.0, 0.0, 0.0, 0.0, 0.0};
    // acc[0]=conf_sumsq acc[1]=conf_corr acc[2]=box acc[3]=cls acc[4]=n

    // ---- dense pass: front-batched independent float4 loads (MLP=4..5) ----
    {
        const float4* __restrict__ p4 = reinterpret_cast<const float4*>(pred);
        const int g0 = conf_addr(tid);
        const int g1 = conf_addr(tid + NTH);
        const int g2 = conf_addr(tid + 2*NTH);
        const int g3 = conf_addr(tid + 3*NTH);
        const bool extra = (tid < REM);
        const int g4 = conf_addr(tid + 4*NTH);

        float4 x0 = __ldg(&p4[g0]);
        float4 x1 = __ldg(&p4[g1]);
        float4 x2 = __ldg(&p4[g2]);
        float4 x3 = __ldg(&p4[g3]);
        float4 x4 = extra ? __ldg(&p4[g4]) : make_float4(0.f, 0.f, 0.f, 0.f);

        float local = ssq4(x0) + ssq4(x1) + ssq4(x2) + ssq4(x3);
        if (extra) local += ssq4(x4);
        acc[0] = (double)local;
    }

    // ---- sparse pass: one item per (target, anchor); 1536 items ----
    if (tid < NT * Anch) {
        int t = tid / Anch;
        int a = tid - t * Anch;
        float tb = targets[t*6 + 0];
        float tc = targets[t*6 + 1];
        float tx = targets[t*6 + 2];
        float ty = targets[t*6 + 3];
        float tw = targets[t*6 + 4];
        float th = targets[t*6 + 5];
        int b  = (int)tb;
        int c  = (int)tc;
        int gx = (int)(tx * (float)Wd);
        int gy = (int)(ty * (float)Hd);
        if (gx >= 0 && gx < Wd && gy >= 0 && gy < Hd && b >= 0 && b < Bsz) {
            const float* base = pred + (size_t)(b * 24 + a * 8) * PLANE
                                     + (size_t)gy * Wd + gx;
            float p0 = base[0*PLANE];
            float p1 = base[1*PLANE];
            float p2 = base[2*PLANE];
            float p3 = base[3*PLANE];
            float p4v = base[4*PLANE];
            float p5 = base[5*PLANE];
            float p6 = base[6*PLANE];
            float p7 = base[7*PLANE];

            float bx = sigm(p0) - tx;
            float by = sigm(p1) - ty;
            float bw = __expf(p2) - tw;
            float bh = __expf(p3) - th;
            acc[2] = (double)(bx*bx + by*by + bw*bw + bh*bh);

            float s4 = sigm(p4v);
            acc[1] = (double)(1.0f - 2.0f * s4);      // (s-1)^2 - s^2

            float t0 = (c == 0) ? 1.0f : 0.0f;
            float t1 = (c == 1) ? 1.0f : 0.0f;
            float t2 = (c == 2) ? 1.0f : 0.0f;
            float d0 = sigm(p5) - t0;
            float d1 = sigm(p6) - t1;
            float d2 = sigm(p7) - t2;
            acc[3] = (double)(d0*d0 + d1*d1 + d2*d2);

            acc[4] = 1.0;
        }
    }

    // ---- block reduction: warp shuffles, then shared ----
    #pragma unroll
    for (int o = 16; o > 0; o >>= 1)
        #pragma unroll
        for (int i = 0; i < 5; i++)
            acc[i] += __shfl_down_sync(0xFFFFFFFFu, acc[i], o);

    __shared__ double sh[NWARPS][5];
    __shared__ int is_last;
    int wid = threadIdx.x >> 5;
    int lid = threadIdx.x & 31;
    if (lid == 0)
        #pragma unroll
        for (int i = 0; i < 5; i++) sh[wid][i] = acc[i];
    __syncthreads();

    if (threadIdx.x == 0) {
        double tot[5] = {0,0,0,0,0};
        #pragma unroll
        for (int w = 0; w < NWARPS; w++)
            #pragma unroll
            for (int i = 0; i < 5; i++) tot[i] += sh[w][i];
        #pragma unroll
        for (int i = 0; i < 5; i++)
            g_partial[blockIdx.x * 5 + i] = tot[i];
        __threadfence();
        unsigned int old = atomicAdd(&g_done, 1u);
        is_last = (old == (unsigned)(gridDim.x - 1)) ? 1 : 0;
    }
    __syncthreads();

    // ---- last block reduces all partials and finalizes ----
    if (is_last) {
        double fin[5] = {0,0,0,0,0};
        if (threadIdx.x < NBLOCK) {
            #pragma unroll
            for (int k = 0; k < 5; k++)
                fin[k] = __ldcg(&g_partial[threadIdx.x * 5 + k]);
        }
        #pragma unroll
        for (int o = 16; o > 0; o >>= 1)
            #pragma unroll
            for (int k = 0; k < 5; k++)
                fin[k] += __shfl_down_sync(0xFFFFFFFFu, fin[k], o);
        if (lid == 0)
            #pragma unroll
            for (int k = 0; k < 5; k++) sh[wid][k] = fin[k];
        __syncthreads();
        if (threadIdx.x == 0) {
            double tot[5] = {0,0,0,0,0};
            #pragma unroll
            for (int w = 0; w < NWARPS; w++)
                #pragma unroll
                for (int k = 0; k < 5; k++) tot[k] += sh[w][k];
            double loss_conf = (tot[0] + tot[1]) / (double)CONF_ELEMS;
            double loss_box  = tot[2] / (tot[4] * 4.0);
            double loss_cls  = tot[3] / (tot[4] * (double)NCLS);
            out[0] = (float)(5.0 * loss_box + loss_conf + loss_cls);
            g_done = 0u;                // reset for next graph replay
        }
    }
}

extern "C" void kernel_launch(void* const* d_in, const int* in_sizes, int n_in,
                              void* d_out, int out_size)
{
    const float* pred    = (const float*)d_in[0];
    const float* targets = (const float*)d_in[1];
    float* out = (float*)d_out;
    detection_loss_kernel<<<NBLOCK, NTHREAD>>>(pred, targets, out);
}

// round 8
// speedup vs baseline: 1.6151x; 1.6151x over previous
#include <cuda_runtime.h>

#define Bsz     32
#define Anch    3
#define Hd      160
#define Wd      160
#define NT      512
#define NCLS    3
#define PLANE   (Hd*Wd)                 // 25600
#define CONF_ELEMS (Bsz*Anch*PLANE)     // 2,457,600
#define CONF_V4 (CONF_ELEMS/4)          // 614,400
#define PLANE_V4 (PLANE/4)              // 6400

#define NBLOCK  296
#define NTHREAD 256
#define NTH     (NBLOCK*NTHREAD)        // 75,776
#define NWARPS  (NTHREAD/32)            // 8
#define REM     (CONF_V4 - 8*NTH)       // 8,192

// per-block partial sums: [block][0..4] = conf_ss, conf_corr, box, cls, n
__device__ double g_partial[NBLOCK * 5];
__device__ unsigned int g_done;

__device__ __forceinline__ float tanh_fast(float x) {
    float y;
    asm("tanh.approx.f32 %0, %1;" : "=f"(y) : "f"(x));
    return y;
}
// sigmoid via single MUFU.TANH: sigma(x) = 0.5 + 0.5*tanh(x/2)
__device__ __forceinline__ float sigm(float x) {
    return fmaf(0.5f, tanh_fast(0.5f * x), 0.5f);
}

__device__ __forceinline__ int conf_addr(int idx) {
    // conf plane p = b*3+a lives at channel 8*p+4 -> float4 index mapping
    return idx + (idx / PLANE_V4) * 44800 + 25600;
}

#define LDG4(dst, ptr)                                                        \
    asm volatile("ld.global.nc.v4.f32 {%0,%1,%2,%3}, [%4];"                   \
                 : "=f"(dst.x), "=f"(dst.y), "=f"(dst.z), "=f"(dst.w)         \
                 : "l"(ptr))

__device__ __forceinline__ float ssq4(float4 v) {
    float s0 = sigm(v.x), s1 = sigm(v.y), s2 = sigm(v.z), s3 = sigm(v.w);
    return s0*s0 + s1*s1 + s2*s2 + s3*s3;
}

__global__ void __launch_bounds__(NTHREAD)
detection_loss_kernel(const float* __restrict__ pred,
                      const float* __restrict__ targets,
                      float* __restrict__ out)
{
    const int tid = blockIdx.x * NTHREAD + threadIdx.x;

    double acc[5] = {0.0, 0.0, 0.0, 0.0, 0.0};
    // acc[0]=conf_sumsq acc[1]=conf_corr acc[2]=box acc[3]=cls acc[4]=n

    // ---- dense pass: 8 front-batched (asm, unsinkable) float4 loads ----
    {
        const float4* __restrict__ p4 = reinterpret_cast<const float4*>(pred);
        const float4* a0 = p4 + conf_addr(tid);
        const float4* a1 = p4 + conf_addr(tid + 1*NTH);
        const float4* a2 = p4 + conf_addr(tid + 2*NTH);
        const float4* a3 = p4 + conf_addr(tid + 3*NTH);
        const float4* a4 = p4 + conf_addr(tid + 4*NTH);
        const float4* a5 = p4 + conf_addr(tid + 5*NTH);
        const float4* a6 = p4 + conf_addr(tid + 6*NTH);
        const float4* a7 = p4 + conf_addr(tid + 7*NTH);

        float4 x0, x1, x2, x3, x4, x5, x6, x7;
        LDG4(x0, a0); LDG4(x1, a1); LDG4(x2, a2); LDG4(x3, a3);
        LDG4(x4, a4); LDG4(x5, a5); LDG4(x6, a6); LDG4(x7, a7);

        float local = ssq4(x0) + ssq4(x1) + ssq4(x2) + ssq4(x3)
                    + ssq4(x4) + ssq4(x5) + ssq4(x6) + ssq4(x7);

        if (tid < REM) {
            const float4* a8 = p4 + conf_addr(tid + 8*NTH);
            float4 x8;
            LDG4(x8, a8);
            local += ssq4(x8);
        }
        acc[0] = (double)local;
    }

    // ---- sparse pass: one item per (target, anchor); 1536 items ----
    if (tid < NT * Anch) {
        int t = tid / Anch;
        int a = tid - t * Anch;
        float tb = targets[t*6 + 0];
        float tc = targets[t*6 + 1];
        float tx = targets[t*6 + 2];
        float ty = targets[t*6 + 3];
        float tw = targets[t*6 + 4];
        float th = targets[t*6 + 5];
        int b  = (int)tb;
        int c  = (int)tc;
        int gx = (int)(tx * (float)Wd);
        int gy = (int)(ty * (float)Hd);
        if (gx >= 0 && gx < Wd && gy >= 0 && gy < Hd && b >= 0 && b < Bsz) {
            const float* base = pred + (size_t)(b * 24 + a * 8) * PLANE
                                     + (size_t)gy * Wd + gx;
            float p0 = base[0*PLANE];
            float p1 = base[1*PLANE];
            float p2 = base[2*PLANE];
            float p3 = base[3*PLANE];
            float p4v = base[4*PLANE];
            float p5 = base[5*PLANE];
            float p6 = base[6*PLANE];
            float p7 = base[7*PLANE];

            float bx = sigm(p0) - tx;
            float by = sigm(p1) - ty;
            float bw = __expf(p2) - tw;
            float bh = __expf(p3) - th;
            acc[2] = (double)(bx*bx + by*by + bw*bw + bh*bh);

            float s4 = sigm(p4v);
            acc[1] = (double)(1.0f - 2.0f * s4);      // (s-1)^2 - s^2

            float t0 = (c == 0) ? 1.0f : 0.0f;
            float t1 = (c == 1) ? 1.0f : 0.0f;
            float t2 = (c == 2) ? 1.0f : 0.0f;
            float d0 = sigm(p5) - t0;
            float d1 = sigm(p6) - t1;
            float d2 = sigm(p7) - t2;
            acc[3] = (double)(d0*d0 + d1*d1 + d2*d2);

            acc[4] = 1.0;
        }
    }

    // ---- block reduction: warp shuffles, then shared ----
    #pragma unroll
    for (int o = 16; o > 0; o >>= 1)
        #pragma unroll
        for (int i = 0; i < 5; i++)
            acc[i] += __shfl_down_sync(0xFFFFFFFFu, acc[i], o);

    __shared__ double sh[NWARPS][5];
    __shared__ int is_last;
    int wid = threadIdx.x >> 5;
    int lid = threadIdx.x & 31;
    if (lid == 0)
        #pragma unroll
        for (int i = 0; i < 5; i++) sh[wid][i] = acc[i];
    __syncthreads();

    if (threadIdx.x == 0) {
        double tot[5] = {0,0,0,0,0};
        #pragma unroll
        for (int w = 0; w < NWARPS; w++)
            #pragma unroll
            for (int i = 0; i < 5; i++) tot[i] += sh[w][i];
        #pragma unroll
        for (int i = 0; i < 5; i++)
            g_partial[blockIdx.x * 5 + i] = tot[i];
        __threadfence();
        unsigned int old = atomicAdd(&g_done, 1u);
        is_last = (old == (unsigned)(gridDim.x - 1)) ? 1 : 0;
    }
    __syncthreads();

    // ---- last block reduces all partials and finalizes ----
    if (is_last) {
        double fin[5] = {0,0,0,0,0};
        for (int i = threadIdx.x; i < NBLOCK; i += NTHREAD) {
            #pragma unroll
            for (int k = 0; k < 5; k++)
                fin[k] += __ldcg(&g_partial[i * 5 + k]);
        }
        #pragma unroll
        for (int o = 16; o > 0; o >>= 1)
            #pragma unroll
            for (int k = 0; k < 5; k++)
                fin[k] += __shfl_down_sync(0xFFFFFFFFu, fin[k], o);
        if (lid == 0)
            #pragma unroll
            for (int k = 0; k < 5; k++) sh[wid][k] = fin[k];
        __syncthreads();
        if (threadIdx.x == 0) {
            double tot[5] = {0,0,0,0,0};
            #pragma unroll
            for (int w = 0; w < NWARPS; w++)
                #pragma unroll
                for (int k = 0; k < 5; k++) tot[k] += sh[w][k];
            double loss_conf = (tot[0] + tot[1]) / (double)CONF_ELEMS;
            double loss_box  = tot[2] / (tot[4] * 4.0);
            double loss_cls  = tot[3] / (tot[4] * (double)NCLS);
            out[0] = (float)(5.0 * loss_box + loss_conf + loss_cls);
            g_done = 0u;                // reset for next graph replay
        }
    }
}

extern "C" void kernel_launch(void* const* d_in, const int* in_sizes, int n_in,
                              void* d_out, int out_size)
{
    const float* pred    = (const float*)d_in[0];
    const float* targets = (const float*)d_in[1];
    float* out = (float*)d_out;
    detection_loss_kernel<<<NBLOCK, NTHREAD>>>(pred, targets, out);
}

// round 9
// speedup vs baseline: 2.1454x; 1.3283x over previous
#include <cuda_runtime.h>

#define Bsz     32
#define Anch    3
#define Hd      160
#define Wd      160
#define NT      512
#define NCLS    3
#define PLANE   (Hd*Wd)                 // 25600
#define CONF_ELEMS (Bsz*Anch*PLANE)     // 2,457,600
#define PLANE_V4 (PLANE/4)              // 6400

#define NBLOCK  150
#define NTHREAD 256
#define NTH     (NBLOCK*NTHREAD)        // 38400 = 6 * PLANE_V4
#define NWARPS  (NTHREAD/32)            // 8
#define JSTEP   16                      // 16 * 38400 = 614400 = CONF_V4 exactly
#define STRIDE4 307200                  // 6 planes * 51200 float4 per plane-step

// per-block partials: [block][0..4] = conf_ss(u^2 sum), conf_corr, box, cls, n
__device__ float g_partial[NBLOCK][5];

__device__ __forceinline__ float tanh_fast(float x) {
    float y;
    asm("tanh.approx.f32 %0, %1;" : "=f"(y) : "f"(x));
    return y;
}
// sigmoid(x) = 0.5 + 0.5*tanh(0.5x) : one MUFU
__device__ __forceinline__ float sigm(float x) {
    return fmaf(0.5f, tanh_fast(0.5f * x), 0.5f);
}

#define LDG4(dst, ptr)                                                        \
    asm volatile("ld.global.nc.v4.f32 {%0,%1,%2,%3}, [%4];"                   \
                 : "=f"(dst.x), "=f"(dst.y), "=f"(dst.z), "=f"(dst.w)         \
                 : "l"(ptr))

// accumulate (1+tanh(x/2))^2 ; caller scales by 0.25 once at the end
__device__ __forceinline__ void usq4(float4 v, float& acc) {
    float u0 = 1.0f + tanh_fast(0.5f * v.x);
    float u1 = 1.0f + tanh_fast(0.5f * v.y);
    float u2 = 1.0f + tanh_fast(0.5f * v.z);
    float u3 = 1.0f + tanh_fast(0.5f * v.w);
    acc = fmaf(u0, u0, acc);
    acc = fmaf(u1, u1, acc);
    acc = fmaf(u2, u2, acc);
    acc = fmaf(u3, u3, acc);
}

__global__ void __launch_bounds__(NTHREAD)
detection_loss_main(const float* __restrict__ pred,
                    const float* __restrict__ targets)
{
    const int tid = blockIdx.x * NTHREAD + threadIdx.x;

    float acc[5] = {0.f, 0.f, 0.f, 0.f, 0.f};
    // [0]=sum u^2 (scaled later) [1]=conf_corr [2]=box [3]=cls [4]=n

    // ---- dense pass: planes 6j + q, q = tid/6400, one div total ----
    {
        const int q = tid / PLANE_V4;            // 0..5
        const int r = tid - q * PLANE_V4;        // 0..6399
        const float4* p = reinterpret_cast<const float4*>(pred)
                        + (size_t)(51200 * q + 25600 + r);

        float4 x0,x1,x2,x3,x4,x5,x6,x7,x8,x9,xa,xb,xc,xd,xe,xf;
        LDG4(x0, p);               LDG4(x1, p + 1*STRIDE4);
        LDG4(x2, p + 2*STRIDE4);   LDG4(x3, p + 3*STRIDE4);
        LDG4(x4, p + 4*STRIDE4);   LDG4(x5, p + 5*STRIDE4);
        LDG4(x6, p + 6*STRIDE4);   LDG4(x7, p + 7*STRIDE4);
        LDG4(x8, p + 8*STRIDE4);   LDG4(x9, p + 9*STRIDE4);
        LDG4(xa, p + 10*STRIDE4);  LDG4(xb, p + 11*STRIDE4);
        LDG4(xc, p + 12*STRIDE4);  LDG4(xd, p + 13*STRIDE4);
        LDG4(xe, p + 14*STRIDE4);  LDG4(xf, p + 15*STRIDE4);

        float s = 0.f;
        usq4(x0, s); usq4(x1, s); usq4(x2, s); usq4(x3, s);
        usq4(x4, s); usq4(x5, s); usq4(x6, s); usq4(x7, s);
        usq4(x8, s); usq4(x9, s); usq4(xa, s); usq4(xb, s);
        usq4(xc, s); usq4(xd, s); usq4(xe, s); usq4(xf, s);
        acc[0] = 0.25f * s;                    // scale (1+t)^2 -> sigmoid^2
    }

    // ---- sparse pass: one item per (target, anchor); 1536 items ----
    if (tid < NT * Anch) {
        int t = tid / Anch;
        int a = tid - t * Anch;
        float tb = targets[t*6 + 0];
        float tc = targets[t*6 + 1];
        float tx = targets[t*6 + 2];
        float ty = targets[t*6 + 3];
        float tw = targets[t*6 + 4];
        float th = targets[t*6 + 5];
        int b  = (int)tb;
        int c  = (int)tc;
        int gx = (int)(tx * (float)Wd);
        int gy = (int)(ty * (float)Hd);
        if (gx >= 0 && gx < Wd && gy >= 0 && gy < Hd && b >= 0 && b < Bsz) {
            const float* base = pred + (size_t)(b * 24 + a * 8) * PLANE
                                     + (size_t)gy * Wd + gx;
            float p0 = base[0*PLANE];
            float p1 = base[1*PLANE];
            float p2 = base[2*PLANE];
            float p3 = base[3*PLANE];
            float p4v = base[4*PLANE];
            float p5 = base[5*PLANE];
            float p6 = base[6*PLANE];
            float p7 = base[7*PLANE];

            float bx = sigm(p0) - tx;
            float by = sigm(p1) - ty;
            float bw = __expf(p2) - tw;
            float bh = __expf(p3) - th;
            acc[2] = bx*bx + by*by + bw*bw + bh*bh;

            acc[1] = 1.0f - 2.0f * sigm(p4v);        // (s-1)^2 - s^2

            float t0 = (c == 0) ? 1.0f : 0.0f;
            float t1 = (c == 1) ? 1.0f : 0.0f;
            float t2 = (c == 2) ? 1.0f : 0.0f;
            float d0 = sigm(p5) - t0;
            float d1 = sigm(p6) - t1;
            float d2 = sigm(p7) - t2;
            acc[3] = d0*d0 + d1*d1 + d2*d2;

            acc[4] = 1.0f;
        }
    }

    // ---- block reduction: float warp shuffles, then shared ----
    #pragma unroll
    for (int o = 16; o > 0; o >>= 1)
        #pragma unroll
        for (int i = 0; i < 5; i++)
            acc[i] += __shfl_down_sync(0xFFFFFFFFu, acc[i], o);

    __shared__ float sh[NWARPS][5];
    int wid = threadIdx.x >> 5;
    int lid = threadIdx.x & 31;
    if (lid == 0)
        #pragma unroll
        for (int i = 0; i < 5; i++) sh[wid][i] = acc[i];
    __syncthreads();

    if (threadIdx.x == 0) {
        float tot[5] = {0.f, 0.f, 0.f, 0.f, 0.f};
        #pragma unroll
        for (int w = 0; w < NWARPS; w++)
            #pragma unroll
            for (int i = 0; i < 5; i++) tot[i] += sh[w][i];
        #pragma unroll
        for (int i = 0; i < 5; i++)
            g_partial[blockIdx.x][i] = tot[i];
    }
}

__global__ void __launch_bounds__(256)
detection_loss_finalize(float* __restrict__ out)
{
    int t = threadIdx.x;
    float v[5] = {0.f, 0.f, 0.f, 0.f, 0.f};
    if (t < NBLOCK) {
        #pragma unroll
        for (int k = 0; k < 5; k++) v[k] = g_partial[t][k];
    }
    #pragma unroll
    for (int o = 16; o > 0; o >>= 1)
        #pragma unroll
        for (int k = 0; k < 5; k++)
            v[k] += __shfl_down_sync(0xFFFFFFFFu, v[k], o);

    __shared__ float sh[8][5];
    int wid = t >> 5;
    if ((t & 31) == 0)
        #pragma unroll
        for (int k = 0; k < 5; k++) sh[wid][k] = v[k];
    __syncthreads();

    if (t == 0) {
        double tot[5] = {0, 0, 0, 0, 0};
        #pragma unroll
        for (int w = 0; w < 8; w++)
            #pragma unroll
            for (int k = 0; k < 5; k++) tot[k] += (double)sh[w][k];
        double loss_conf = (tot[0] + tot[1]) / (double)CONF_ELEMS;
        double loss_box  = tot[2] / (tot[4] * 4.0);
        double loss_cls  = tot[3] / (tot[4] * (double)NCLS);
        out[0] = (float)(5.0 * loss_box + loss_conf + loss_cls);
    }
}

extern "C" void kernel_launch(void* const* d_in, const int* in_sizes, int n_in,
                              void* d_out, int out_size)
{
    const float* pred    = (const float*)d_in[0];
    const float* targets = (const float*)d_in[1];
    float* out = (float*)d_out;
    detection_loss_main<<<NBLOCK, NTHREAD>>>(pred, targets);
    detection_loss_finalize<<<1, 256>>>(out);
}